// round 1
// baseline (speedup 1.0000x reference)
#include <cuda_runtime.h>

#define N_NODES 100000
#define E_EDGES 1000000
#define H_DIM   64
#define OUT_DIM 16
#define R_REL   90
#define B_BAS   8
#define EPB     256   // edges per block in edge kernels

// ---------------- device scratch (no allocations allowed) ----------------
__device__ float g_W0[R_REL * H_DIM * H_DIM];
__device__ float g_W1[R_REL * H_DIM * H_DIM];
__device__ float g_W2[R_REL * H_DIM * OUT_DIM];
__device__ int   g_cnt[R_REL];
__device__ int   g_off[R_REL + 1];
__device__ int   g_cur[R_REL];
__device__ int   g_ssrc[E_EDGES];
__device__ int   g_sdst[E_EDGES];
__device__ int   g_srel[E_EDGES];
__device__ float g_snorm[E_EDGES];
__device__ float g_h1[N_NODES * H_DIM];
__device__ float g_h2[N_NODES * H_DIM];

// ---------------- sorting (counting sort by relation) ----------------
__global__ void k_zero_cnt() {
    if (threadIdx.x < R_REL) g_cnt[threadIdx.x] = 0;
}

__global__ void k_hist(const int* __restrict__ et) {
    int e = blockIdx.x * blockDim.x + threadIdx.x;
    if (e < E_EDGES) atomicAdd(&g_cnt[et[e]], 1);
}

__global__ void k_scan() {
    if (threadIdx.x == 0) {
        int s = 0;
        for (int r = 0; r < R_REL; r++) {
            g_off[r] = s; g_cur[r] = s; s += g_cnt[r];
        }
        g_off[R_REL] = s;
    }
}

__global__ void k_scatter(const int* __restrict__ src, const int* __restrict__ dst,
                          const int* __restrict__ et, const float* __restrict__ norm) {
    int e = blockIdx.x * blockDim.x + threadIdx.x;
    if (e < E_EDGES) {
        int r = et[e];
        int p = atomicAdd(&g_cur[r], 1);
        g_ssrc[p] = src[e];
        g_sdst[p] = dst[e];
        g_srel[p] = r;
        g_snorm[p] = norm[e];
    }
}

// ---------------- W_r = sum_b coeff[r,b] * bases[b]  ----------------
template <int OD>
__global__ void k_W(const float* __restrict__ coeff, const float* __restrict__ bases,
                    int which) {
    float* W = (which == 0) ? g_W0 : (which == 1) ? g_W1 : g_W2;
    int idx = blockIdx.x * blockDim.x + threadIdx.x;
    if (idx >= R_REL * H_DIM * OD) return;
    int r  = idx / (H_DIM * OD);
    int io = idx - r * (H_DIM * OD);
    float s = 0.f;
#pragma unroll
    for (int b = 0; b < B_BAS; b++)
        s = fmaf(coeff[r * B_BAS + b], bases[b * H_DIM * OD + io], s);
    W[idx] = s;
}

// ---------------- init h = bias, relu ----------------
__global__ void k_init64(const float* __restrict__ bias, int hsel) {
    float* h = (hsel == 1) ? g_h1 : g_h2;
    int idx = blockIdx.x * blockDim.x + threadIdx.x;   // over N*H/4
    if (idx < N_NODES * H_DIM / 4)
        ((float4*)h)[idx] = ((const float4*)bias)[idx & 15];
}

__global__ void k_init16(const float* __restrict__ bias, float* __restrict__ h) {
    int idx = blockIdx.x * blockDim.x + threadIdx.x;   // over N*OUT/4
    if (idx < N_NODES * OUT_DIM / 4)
        ((float4*)h)[idx] = ((const float4*)bias)[idx & 3];
}

__global__ void k_relu(int hsel) {
    float* h = (hsel == 1) ? g_h1 : g_h2;
    int idx = blockIdx.x * blockDim.x + threadIdx.x;
    if (idx < N_NODES * H_DIM / 4) {
        float4 v = ((float4*)h)[idx];
        v.x = fmaxf(v.x, 0.f); v.y = fmaxf(v.y, 0.f);
        v.z = fmaxf(v.z, 0.f); v.w = fmaxf(v.w, 0.f);
        ((float4*)h)[idx] = v;
    }
}

// ---------------- edge kernel, H->H layers ----------------
// Block covers EPB consecutive sorted edges; within a relation segment the
// block caches W_r (16 KB) in SMEM. Warp-per-edge: lane owns out[2*lane],
// out[2*lane+1]; x[src] broadcast via shuffles; vectorized red.v2 scatter.
__global__ void __launch_bounds__(256) k_edge64(const float* __restrict__ x_in,
                                                int xsel, int wsel, int hsel) {
    const float* x = (xsel == 0) ? x_in : (xsel == 1) ? g_h1 : g_h2;
    const float* W = (wsel == 0) ? g_W0 : g_W1;
    float* h       = (hsel == 1) ? g_h1 : g_h2;

    __shared__ float Ws[H_DIM * H_DIM];
    const int lane = threadIdx.x & 31;
    const int warp = threadIdx.x >> 5;

    int base = blockIdx.x * EPB;
    int lim  = min(base + EPB, E_EDGES);
    int pos  = base;
    while (pos < lim) {
        int r      = g_srel[pos];
        int segEnd = min(lim, g_off[r + 1]);
        {
            const float4* Wg  = (const float4*)(W + r * (H_DIM * H_DIM));
            float4*       Ws4 = (float4*)Ws;
#pragma unroll
            for (int i = 0; i < 4; i++)
                Ws4[threadIdx.x + i * 256] = Wg[threadIdx.x + i * 256];
        }
        __syncthreads();

        for (int e = pos + warp; e < segEnd; e += 8) {
            int   s   = g_ssrc[e];
            float nrm = g_snorm[e];
            const float* xv = x + s * H_DIM;
            float xr0 = xv[lane]      * nrm;
            float xr1 = xv[lane + 32] * nrm;
            float a0 = 0.f, a1 = 0.f;
#pragma unroll
            for (int i = 0; i < 32; i++) {
                float  xi = __shfl_sync(0xffffffffu, xr0, i);
                float2 w  = *(const float2*)&Ws[i * H_DIM + 2 * lane];
                a0 = fmaf(xi, w.x, a0);
                a1 = fmaf(xi, w.y, a1);
            }
#pragma unroll
            for (int i = 0; i < 32; i++) {
                float  xi = __shfl_sync(0xffffffffu, xr1, i);
                float2 w  = *(const float2*)&Ws[(i + 32) * H_DIM + 2 * lane];
                a0 = fmaf(xi, w.x, a0);
                a1 = fmaf(xi, w.y, a1);
            }
            float* hp = h + g_sdst[e] * H_DIM + 2 * lane;
            asm volatile("red.global.add.v2.f32 [%0], {%1, %2};"
                         :: "l"(hp), "f"(a0), "f"(a1) : "memory");
        }
        __syncthreads();
        pos = segEnd;
    }
}

// ---------------- edge kernel, H->OUT (last layer) ----------------
// Two edges per warp: lanes 0-15 edge A, 16-31 edge B; lane owns one output.
__global__ void __launch_bounds__(256) k_edge16(const float* __restrict__ unused,
                                                float* __restrict__ h) {
    const float* x = g_h2;
    const float* W = g_W2;

    __shared__ float Ws[H_DIM * OUT_DIM];   // 1024 floats
    const int lane = threadIdx.x & 31;
    const int warp = threadIdx.x >> 5;
    const int half = lane >> 4;             // which edge of the pair
    const int o    = lane & 15;             // output column

    int base = blockIdx.x * EPB;
    int lim  = min(base + EPB, E_EDGES);
    int pos  = base;
    while (pos < lim) {
        int r      = g_srel[pos];
        int segEnd = min(lim, g_off[r + 1]);
        {
            const float4* Wg  = (const float4*)(W + r * (H_DIM * OUT_DIM));
            float4*       Ws4 = (float4*)Ws;
            Ws4[threadIdx.x] = Wg[threadIdx.x];   // 256 * 16B = 4KB
        }
        __syncthreads();

        for (int e0 = pos + warp * 2; e0 < segEnd; e0 += 16) {
            int  e     = e0 + half;
            bool valid = (e < segEnd);
            int  ec    = valid ? e : (segEnd - 1);
            int   s    = g_ssrc[ec];
            float nrm  = g_snorm[ec];
            const float* xv = x + s * H_DIM;
            float xr[4];
#pragma unroll
            for (int k = 0; k < 4; k++) xr[k] = xv[k * 16 + o] * nrm;
            float acc = 0.f;
#pragma unroll
            for (int k = 0; k < 4; k++) {
#pragma unroll
                for (int t = 0; t < 16; t++) {
                    float xi = __shfl_sync(0xffffffffu, xr[k], (lane & 16) + t);
                    acc = fmaf(xi, Ws[(k * 16 + t) * OUT_DIM + o], acc);
                }
            }
            if (valid) atomicAdd(h + g_sdst[ec] * OUT_DIM + o, acc);
        }
        __syncthreads();
        pos = segEnd;
    }
}

// ---------------- launch ----------------
extern "C" void kernel_launch(void* const* d_in, const int* in_sizes, int n_in,
                              void* d_out, int out_size) {
    const float* feats  = (const float*)d_in[0];
    const float* coeff0 = (const float*)d_in[1];
    const float* bases0 = (const float*)d_in[2];
    const float* bias0  = (const float*)d_in[3];
    const float* coeff1 = (const float*)d_in[4];
    const float* bases1 = (const float*)d_in[5];
    const float* bias1  = (const float*)d_in[6];
    const float* coeff2 = (const float*)d_in[7];
    const float* bases2 = (const float*)d_in[8];
    const float* bias2  = (const float*)d_in[9];
    const int*   src    = (const int*)d_in[10];
    const int*   dst    = (const int*)d_in[11];
    const int*   etype  = (const int*)d_in[12];
    const float* norm   = (const float*)d_in[13];
    float*       out    = (float*)d_out;

    const int EB = (E_EDGES + 255) / 256;          // 3907

    // one-time (per replay) structure build
    k_zero_cnt<<<1, 128>>>();
    k_hist<<<EB, 256>>>(etype);
    k_scan<<<1, 32>>>();
    k_scatter<<<EB, 256>>>(src, dst, etype, norm);

    // relation weight matrices
    k_W<H_DIM><<<(R_REL * H_DIM * H_DIM + 255) / 256, 256>>>(coeff0, bases0, 0);
    k_W<H_DIM><<<(R_REL * H_DIM * H_DIM + 255) / 256, 256>>>(coeff1, bases1, 1);
    k_W<OUT_DIM><<<(R_REL * H_DIM * OUT_DIM + 255) / 256, 256>>>(coeff2, bases2, 2);

    const int NB64 = (N_NODES * H_DIM / 4 + 255) / 256;    // 6250
    const int NB16 = (N_NODES * OUT_DIM / 4 + 255) / 256;  // 1563

    // layer 0: feats -> g_h1 (relu)
    k_init64<<<NB64, 256>>>(bias0, 1);
    k_edge64<<<EB, 256>>>(feats, /*xsel=*/0, /*wsel=*/0, /*hsel=*/1);
    k_relu<<<NB64, 256>>>(1);

    // layer 1: g_h1 -> g_h2 (relu)
    k_init64<<<NB64, 256>>>(bias1, 2);
    k_edge64<<<EB, 256>>>(feats, /*xsel=*/1, /*wsel=*/1, /*hsel=*/2);
    k_relu<<<NB64, 256>>>(2);

    // layer 2: g_h2 -> out (no relu)
    k_init16<<<NB16, 256>>>(bias2, out);
    k_edge16<<<EB, 256>>>(feats, out);
}

// round 2
// speedup vs baseline: 2.4121x; 2.4121x over previous
#include <cuda_runtime.h>

#define N_NODES 100000
#define E_EDGES 1000000
#define H_DIM   64
#define OUT_DIM 16
#define R_REL   90
#define B_BAS   8
#define SC_EPB  2048   // edges per block in hist/scatter

// ---------------- device scratch (no allocations allowed) ----------------
__device__ float g_W0[R_REL * H_DIM * H_DIM];
__device__ float g_W1[R_REL * H_DIM * H_DIM];
__device__ float g_W2[R_REL * H_DIM * OUT_DIM];
__device__ int   g_cnt[R_REL];
__device__ int   g_off[R_REL + 1];
__device__ int   g_cur[R_REL];
__device__ int4  g_edges[E_EDGES];           // (src, dst, rel, norm-as-int)
__device__ float g_h1[N_NODES * H_DIM];
__device__ float g_h2[N_NODES * H_DIM];

// ---------------- counting sort by relation (block-local ranks) ----------------
__global__ void k_zero_cnt() {
    if (threadIdx.x < R_REL) g_cnt[threadIdx.x] = 0;
}

__global__ void __launch_bounds__(256) k_hist(const int* __restrict__ et) {
    __shared__ int h[R_REL];
    int t = threadIdx.x;
    for (int i = t; i < R_REL; i += 256) h[i] = 0;
    __syncthreads();
    int base = blockIdx.x * SC_EPB;
#pragma unroll
    for (int i = 0; i < 8; i++) {
        int e = base + i * 256 + t;
        if (e < E_EDGES) atomicAdd(&h[et[e]], 1);
    }
    __syncthreads();
    for (int i = t; i < R_REL; i += 256)
        if (h[i]) atomicAdd(&g_cnt[i], h[i]);
}

__global__ void k_scan() {
    if (threadIdx.x == 0) {
        int s = 0;
        for (int r = 0; r < R_REL; r++) {
            g_off[r] = s; g_cur[r] = s; s += g_cnt[r];
        }
        g_off[R_REL] = s;
    }
}

__global__ void __launch_bounds__(256) k_scatter(const int* __restrict__ src,
                                                 const int* __restrict__ dst,
                                                 const int* __restrict__ et,
                                                 const float* __restrict__ norm) {
    __shared__ int scnt[R_REL];
    __shared__ int sbase[R_REL];
    int t = threadIdx.x;
    for (int i = t; i < R_REL; i += 256) scnt[i] = 0;
    __syncthreads();
    int base = blockIdx.x * SC_EPB;
    int r[8], rk[8];
#pragma unroll
    for (int i = 0; i < 8; i++) {
        int e = base + i * 256 + t;
        if (e < E_EDGES) {
            r[i]  = et[e];
            rk[i] = atomicAdd(&scnt[r[i]], 1);
        } else r[i] = -1;
    }
    __syncthreads();
    for (int i = t; i < R_REL; i += 256)
        sbase[i] = scnt[i] ? atomicAdd(&g_cur[i], scnt[i]) : 0;
    __syncthreads();
#pragma unroll
    for (int i = 0; i < 8; i++) {
        int e = base + i * 256 + t;
        if (r[i] >= 0) {
            int p = sbase[r[i]] + rk[i];
            g_edges[p] = make_int4(src[e], dst[e], r[i], __float_as_int(norm[e]));
        }
    }
}

// ---------------- W_r = sum_b coeff[r,b] * bases[b]  ----------------
template <int OD>
__global__ void k_W(const float* __restrict__ coeff, const float* __restrict__ bases,
                    int which) {
    float* W = (which == 0) ? g_W0 : (which == 1) ? g_W1 : g_W2;
    int idx = blockIdx.x * blockDim.x + threadIdx.x;
    if (idx >= R_REL * H_DIM * OD) return;
    int r  = idx / (H_DIM * OD);
    int io = idx - r * (H_DIM * OD);
    float s = 0.f;
#pragma unroll
    for (int b = 0; b < B_BAS; b++)
        s = fmaf(coeff[r * B_BAS + b], bases[b * H_DIM * OD + io], s);
    W[idx] = s;
}

// ---------------- init h = bias ----------------
__global__ void k_init64(const float* __restrict__ bias, float* __restrict__ h) {
    int idx = blockIdx.x * blockDim.x + threadIdx.x;   // over N*H/4
    if (idx < N_NODES * H_DIM / 4)
        ((float4*)h)[idx] = ((const float4*)bias)[idx & 15];
}

__global__ void k_init16(const float* __restrict__ bias, float* __restrict__ h) {
    int idx = blockIdx.x * blockDim.x + threadIdx.x;   // over N*OUT/4
    if (idx < N_NODES * OUT_DIM / 4)
        ((float4*)h)[idx] = ((const float4*)bias)[idx & 3];
}

// ---------------- edge kernel, H->H: thread-per-edge, W broadcast ----------------
template <bool RELU>
__global__ void __launch_bounds__(256, 2) k_edge64(const float* __restrict__ x,
                                                   const float* __restrict__ W,
                                                   float* __restrict__ h) {
    __shared__ float Ws[H_DIM * H_DIM];
    int base = blockIdx.x * 256;
    int lim  = min(base + 256, E_EDGES);
    int pos  = base;
    while (pos < lim) {
        int4 e0 = g_edges[pos];           // uniform broadcast read
        int  r  = e0.z;
        int  segEnd = min(lim, g_off[r + 1]);
        {
            const float4* Wg  = (const float4*)(W + r * (H_DIM * H_DIM));
            float4*       Ws4 = (float4*)Ws;
#pragma unroll
            for (int i = 0; i < 4; i++)
                Ws4[threadIdx.x + i * 256] = Wg[threadIdx.x + i * 256];
        }
        __syncthreads();

        int e = pos + threadIdx.x;
        if (e < segEnd) {
            int4  ed  = g_edges[e];
            const float* xv = x + ed.x * H_DIM;
            float nrm = __int_as_float(ed.w);
            float acc[H_DIM];
#pragma unroll
            for (int o = 0; o < H_DIM; o++) acc[o] = 0.f;

            for (int ic = 0; ic < 8; ic++) {        // not unrolled (I$)
                float4 xa = *(const float4*)(xv + ic * 8);
                float4 xb = *(const float4*)(xv + ic * 8 + 4);
                float xs[8] = {xa.x, xa.y, xa.z, xa.w, xb.x, xb.y, xb.z, xb.w};
#pragma unroll
                for (int i = 0; i < 8; i++) {
                    float xi = RELU ? fmaxf(xs[i], 0.f) : xs[i];
                    xi *= nrm;
#pragma unroll
                    for (int o = 0; o < H_DIM; o += 4) {
                        float4 w = *(const float4*)&Ws[(ic * 8 + i) * H_DIM + o];
                        acc[o]     = fmaf(xi, w.x, acc[o]);
                        acc[o + 1] = fmaf(xi, w.y, acc[o + 1]);
                        acc[o + 2] = fmaf(xi, w.z, acc[o + 2]);
                        acc[o + 3] = fmaf(xi, w.w, acc[o + 3]);
                    }
                }
            }
            float* hp = h + ed.y * H_DIM;
#pragma unroll
            for (int o = 0; o < H_DIM; o += 4)
                asm volatile("red.global.add.v4.f32 [%0], {%1, %2, %3, %4};"
                             :: "l"(hp + o), "f"(acc[o]), "f"(acc[o + 1]),
                                "f"(acc[o + 2]), "f"(acc[o + 3]) : "memory");
        }
        __syncthreads();
        pos = segEnd;
    }
}

// ---------------- edge kernel, H->OUT: thread-per-edge ----------------
__global__ void __launch_bounds__(256, 4) k_edge16(const float* __restrict__ x,
                                                   const float* __restrict__ W,
                                                   float* __restrict__ h) {
    __shared__ float Ws[H_DIM * OUT_DIM];
    int base = blockIdx.x * 256;
    int lim  = min(base + 256, E_EDGES);
    int pos  = base;
    while (pos < lim) {
        int4 e0 = g_edges[pos];
        int  r  = e0.z;
        int  segEnd = min(lim, g_off[r + 1]);
        {
            const float4* Wg  = (const float4*)(W + r * (H_DIM * OUT_DIM));
            float4*       Ws4 = (float4*)Ws;
            Ws4[threadIdx.x] = Wg[threadIdx.x];
        }
        __syncthreads();

        int e = pos + threadIdx.x;
        if (e < segEnd) {
            int4  ed  = g_edges[e];
            const float* xv = x + ed.x * H_DIM;
            float nrm = __int_as_float(ed.w);
            float acc[OUT_DIM];
#pragma unroll
            for (int o = 0; o < OUT_DIM; o++) acc[o] = 0.f;

#pragma unroll
            for (int ic = 0; ic < 8; ic++) {
                float4 xa = *(const float4*)(xv + ic * 8);
                float4 xb = *(const float4*)(xv + ic * 8 + 4);
                float xs[8] = {xa.x, xa.y, xa.z, xa.w, xb.x, xb.y, xb.z, xb.w};
#pragma unroll
                for (int i = 0; i < 8; i++) {
                    float xi = fmaxf(xs[i], 0.f) * nrm;   // relu fused (prev layer)
#pragma unroll
                    for (int o = 0; o < OUT_DIM; o += 4) {
                        float4 w = *(const float4*)&Ws[(ic * 8 + i) * OUT_DIM + o];
                        acc[o]     = fmaf(xi, w.x, acc[o]);
                        acc[o + 1] = fmaf(xi, w.y, acc[o + 1]);
                        acc[o + 2] = fmaf(xi, w.z, acc[o + 2]);
                        acc[o + 3] = fmaf(xi, w.w, acc[o + 3]);
                    }
                }
            }
            float* hp = h + ed.y * OUT_DIM;
#pragma unroll
            for (int o = 0; o < OUT_DIM; o += 4)
                asm volatile("red.global.add.v4.f32 [%0], {%1, %2, %3, %4};"
                             :: "l"(hp + o), "f"(acc[o]), "f"(acc[o + 1]),
                                "f"(acc[o + 2]), "f"(acc[o + 3]) : "memory");
        }
        __syncthreads();
        pos = segEnd;
    }
}

// ---------------- launch ----------------
extern "C" void kernel_launch(void* const* d_in, const int* in_sizes, int n_in,
                              void* d_out, int out_size) {
    const float* feats  = (const float*)d_in[0];
    const float* coeff0 = (const float*)d_in[1];
    const float* bases0 = (const float*)d_in[2];
    const float* bias0  = (const float*)d_in[3];
    const float* coeff1 = (const float*)d_in[4];
    const float* bases1 = (const float*)d_in[5];
    const float* bias1  = (const float*)d_in[6];
    const float* coeff2 = (const float*)d_in[7];
    const float* bases2 = (const float*)d_in[8];
    const float* bias2  = (const float*)d_in[9];
    const int*   src    = (const int*)d_in[10];
    const int*   dst    = (const int*)d_in[11];
    const int*   etype  = (const int*)d_in[12];
    const float* norm   = (const float*)d_in[13];
    float*       out    = (float*)d_out;

    // resolve device-global symbol addresses on host is not allowed in capture;
    // instead pass via kernels that reference the globals directly.
    const int SB = (E_EDGES + SC_EPB - 1) / SC_EPB;   // 489
    const int EB = (E_EDGES + 255) / 256;             // 3907

    // structure build
    k_zero_cnt<<<1, 128>>>();
    k_hist<<<SB, 256>>>(etype);
    k_scan<<<1, 32>>>();
    k_scatter<<<SB, 256>>>(src, dst, etype, norm);

    // relation weight matrices
    k_W<H_DIM><<<(R_REL * H_DIM * H_DIM + 255) / 256, 256>>>(coeff0, bases0, 0);
    k_W<H_DIM><<<(R_REL * H_DIM * H_DIM + 255) / 256, 256>>>(coeff1, bases1, 1);
    k_W<OUT_DIM><<<(R_REL * H_DIM * OUT_DIM + 255) / 256, 256>>>(coeff2, bases2, 2);

    const int NB64 = (N_NODES * H_DIM / 4 + 255) / 256;
    const int NB16 = (N_NODES * OUT_DIM / 4 + 255) / 256;

    // grab raw pointers to the device globals via a tiny helper trick:
    // kernels take them as template-free args using the symbols directly.
    float *h1, *h2, *W0, *W1, *W2;
    cudaGetSymbolAddress((void**)&h1, g_h1);
    cudaGetSymbolAddress((void**)&h2, g_h2);
    cudaGetSymbolAddress((void**)&W0, g_W0);
    cudaGetSymbolAddress((void**)&W1, g_W1);
    cudaGetSymbolAddress((void**)&W2, g_W2);

    // layer 0: feats -> h1 (no relu on input)
    k_init64<<<NB64, 256>>>(bias0, h1);
    k_edge64<false><<<EB, 256>>>(feats, W0, h1);

    // layer 1: relu(h1) -> h2
    k_init64<<<NB64, 256>>>(bias1, h2);
    k_edge64<true><<<EB, 256>>>(h1, W1, h2);

    // layer 2: relu(h2) -> out
    k_init16<<<NB16, 256>>>(bias2, out);
    k_edge16<<<EB, 256>>>(h2, W2, out);
}

// round 3
// speedup vs baseline: 2.6307x; 1.0906x over previous
#include <cuda_runtime.h>

#define N_NODES 100000
#define E_EDGES 1000000
#define H_DIM   64
#define OUT_DIM 16
#define R_REL   90
#define B_BAS   8
#define SC_EPB  2048

// ---------------- device scratch ----------------
__device__ float g_W0[R_REL * H_DIM * H_DIM];
__device__ float g_W1[R_REL * H_DIM * H_DIM];
__device__ float g_W2[R_REL * H_DIM * OUT_DIM];
__device__ int   g_cnt[R_REL];
__device__ int   g_off[R_REL + 1];
__device__ int   g_cur[R_REL];
__device__ int4  g_edges[E_EDGES];           // (src, dst, rel, norm bits)
__device__ float g_h1[N_NODES * H_DIM];
__device__ float g_h2[N_NODES * H_DIM];

// ---------------- counting sort by relation ----------------
__global__ void k_zero_cnt() {
    if (threadIdx.x < R_REL) g_cnt[threadIdx.x] = 0;
}

__global__ void __launch_bounds__(256) k_hist(const int* __restrict__ et) {
    __shared__ int h[R_REL];
    int t = threadIdx.x;
    for (int i = t; i < R_REL; i += 256) h[i] = 0;
    __syncthreads();
    int base = blockIdx.x * SC_EPB;
#pragma unroll
    for (int i = 0; i < 8; i++) {
        int e = base + i * 256 + t;
        if (e < E_EDGES) atomicAdd(&h[et[e]], 1);
    }
    __syncthreads();
    for (int i = t; i < R_REL; i += 256)
        if (h[i]) atomicAdd(&g_cnt[i], h[i]);
}

__global__ void k_scan() {
    if (threadIdx.x == 0) {
        int s = 0;
        for (int r = 0; r < R_REL; r++) {
            g_off[r] = s; g_cur[r] = s; s += g_cnt[r];
        }
        g_off[R_REL] = s;
    }
}

__global__ void __launch_bounds__(256) k_scatter(const int* __restrict__ src,
                                                 const int* __restrict__ dst,
                                                 const int* __restrict__ et,
                                                 const float* __restrict__ norm) {
    __shared__ int scnt[R_REL];
    __shared__ int sbase[R_REL];
    int t = threadIdx.x;
    for (int i = t; i < R_REL; i += 256) scnt[i] = 0;
    __syncthreads();
    int base = blockIdx.x * SC_EPB;
    int r[8], rk[8];
#pragma unroll
    for (int i = 0; i < 8; i++) {
        int e = base + i * 256 + t;
        if (e < E_EDGES) {
            r[i]  = et[e];
            rk[i] = atomicAdd(&scnt[r[i]], 1);
        } else r[i] = -1;
    }
    __syncthreads();
    for (int i = t; i < R_REL; i += 256)
        sbase[i] = scnt[i] ? atomicAdd(&g_cur[i], scnt[i]) : 0;
    __syncthreads();
#pragma unroll
    for (int i = 0; i < 8; i++) {
        int e = base + i * 256 + t;
        if (r[i] >= 0) {
            int p = sbase[r[i]] + rk[i];
            g_edges[p] = make_int4(src[e], dst[e], r[i], __float_as_int(norm[e]));
        }
    }
}

// ---------------- W_r = sum_b coeff[r,b] * bases[b] ----------------
template <int OD>
__global__ void k_W(const float* __restrict__ coeff, const float* __restrict__ bases,
                    int which) {
    float* W = (which == 0) ? g_W0 : (which == 1) ? g_W1 : g_W2;
    int idx = blockIdx.x * blockDim.x + threadIdx.x;
    if (idx >= R_REL * H_DIM * OD) return;
    int r  = idx / (H_DIM * OD);
    int io = idx - r * (H_DIM * OD);
    float s = 0.f;
#pragma unroll
    for (int b = 0; b < B_BAS; b++)
        s = fmaf(coeff[r * B_BAS + b], bases[b * H_DIM * OD + io], s);
    W[idx] = s;
}

// ---------------- init / relu ----------------
__global__ void k_init64(const float* __restrict__ bias, float* __restrict__ h) {
    int idx = blockIdx.x * blockDim.x + threadIdx.x;
    if (idx < N_NODES * H_DIM / 4)
        ((float4*)h)[idx] = ((const float4*)bias)[idx & 15];
}

__global__ void k_init16(const float* __restrict__ bias, float* __restrict__ h) {
    int idx = blockIdx.x * blockDim.x + threadIdx.x;
    if (idx < N_NODES * OUT_DIM / 4)
        ((float4*)h)[idx] = ((const float4*)bias)[idx & 3];
}

__global__ void k_relu(float* __restrict__ h) {
    int idx = blockIdx.x * blockDim.x + threadIdx.x;
    if (idx < N_NODES * H_DIM / 4) {
        float4 v = ((float4*)h)[idx];
        v.x = fmaxf(v.x, 0.f); v.y = fmaxf(v.y, 0.f);
        v.z = fmaxf(v.z, 0.f); v.w = fmaxf(v.w, 0.f);
        ((float4*)h)[idx] = v;
    }
}

// ---------------- f32x2 helpers ----------------
#define FMA2(acc, a, b) \
    asm("fma.rn.f32x2 %0, %1, %2, %0;" : "+l"(acc) : "l"(a), "l"(b))
#define MUL2(acc, b) \
    asm("mul.rn.f32x2 %0, %0, %1;" : "+l"(acc) : "l"(b))
#define DUP2(d, s) \
    asm("mov.b64 %0, {%1, %1};" : "=l"(d) : "r"(__float_as_uint(s)))
#define UNPK2(f0, f1, s) \
    asm("mov.b64 {%0, %1}, %2;" : "=f"(f0), "=f"(f1) : "l"(s))

// ---------------- edge kernel, H->H: 2 edges x 32 outs per thread, f32x2 ----
// Warp: lanes 0-15 handle outs [0,32) of edge-pairs 0..15, lanes 16-31 outs
// [32,64) of the same pairs -> warp covers 32 edges. W in split SMEM copies,
// 16B-offset so the two half-groups hit disjoint banks.
__global__ void __launch_bounds__(256, 2) k_edge64(const float* __restrict__ x,
                                                   const float* __restrict__ W,
                                                   float* __restrict__ h) {
    __shared__ float Ws[H_DIM * 32 + 4 + H_DIM * 32];   // A | pad | B
    float* WsA = Ws;
    float* WsB = Ws + H_DIM * 32 + 4;

    const int tid  = threadIdx.x;
    const int lane = tid & 31;
    const int warp = tid >> 5;
    const int half = lane >> 4;
    const int pidx = lane & 15;

    int base = blockIdx.x * 256;
    int lim  = min(base + 256, E_EDGES);
    int pos  = base;
    while (pos < lim) {
        int r      = g_edges[pos].z;
        int segEnd = min(lim, g_off[r + 1]);
        {
            const float4* Wg = (const float4*)(W + r * (H_DIM * H_DIM));
#pragma unroll
            for (int k = 0; k < 4; k++) {
                int g   = tid + k * 256;       // float4 index 0..1023
                int row = g >> 4, o4 = g & 15;
                float4 v = Wg[g];
                float* d = (o4 < 8) ? &WsA[row * 32 + o4 * 4]
                                    : &WsB[row * 32 + (o4 - 8) * 4];
                *(float4*)d = v;
            }
        }
        __syncthreads();

        int e0 = pos + warp * 32 + 2 * pidx;
        int e1 = e0 + 1;
        if (e0 < segEnd) {
            bool v1  = (e1 < segEnd);
            int4 ed0 = g_edges[e0];
            int4 ed1 = v1 ? g_edges[e1] : ed0;
            const float* x0 = x + ed0.x * H_DIM;
            const float* x1 = x + ed1.x * H_DIM;
            const float* Wh = half ? WsB : WsA;

            unsigned long long acc[32];
#pragma unroll
            for (int j = 0; j < 32; j++) acc[j] = 0ull;

            for (int ic = 0; ic < 8; ic++) {          // not unrolled (I$)
                float4 a0 = *(const float4*)(x0 + ic * 8);
                float4 a1 = *(const float4*)(x0 + ic * 8 + 4);
                float4 b0 = *(const float4*)(x1 + ic * 8);
                float4 b1 = *(const float4*)(x1 + ic * 8 + 4);
                float xs0[8] = {a0.x, a0.y, a0.z, a0.w, a1.x, a1.y, a1.z, a1.w};
                float xs1[8] = {b0.x, b0.y, b0.z, b0.w, b1.x, b1.y, b1.z, b1.w};
#pragma unroll
                for (int i = 0; i < 8; i++) {
                    unsigned long long A0, A1;
                    DUP2(A0, xs0[i]);
                    DUP2(A1, xs1[i]);
                    const float* Wrow = Wh + (ic * 8 + i) * 32;
#pragma unroll
                    for (int j = 0; j < 8; j++) {
                        ulonglong2 w = *(const ulonglong2*)(Wrow + j * 4);
                        FMA2(acc[2 * j],          A0, w.x);
                        FMA2(acc[2 * j + 1],      A0, w.y);
                        FMA2(acc[16 + 2 * j],     A1, w.x);
                        FMA2(acc[16 + 2 * j + 1], A1, w.y);
                    }
                }
            }

            float n0 = __int_as_float(ed0.w);
            float n1 = v1 ? __int_as_float(ed1.w) : 0.f;
            unsigned long long NN0, NN1;
            DUP2(NN0, n0);
            DUP2(NN1, n1);
#pragma unroll
            for (int j = 0; j < 16; j++) MUL2(acc[j], NN0);
#pragma unroll
            for (int j = 16; j < 32; j++) MUL2(acc[j], NN1);

            float* hp0 = h + ed0.y * H_DIM + half * 32;
#pragma unroll
            for (int q = 0; q < 8; q++) {
                float f0, f1, f2, f3;
                UNPK2(f0, f1, acc[2 * q]);
                UNPK2(f2, f3, acc[2 * q + 1]);
                asm volatile("red.global.add.v4.f32 [%0], {%1, %2, %3, %4};"
                             :: "l"(hp0 + q * 4), "f"(f0), "f"(f1), "f"(f2), "f"(f3)
                             : "memory");
            }
            if (v1) {
                float* hp1 = h + ed1.y * H_DIM + half * 32;
#pragma unroll
                for (int q = 0; q < 8; q++) {
                    float f0, f1, f2, f3;
                    UNPK2(f0, f1, acc[16 + 2 * q]);
                    UNPK2(f2, f3, acc[16 + 2 * q + 1]);
                    asm volatile("red.global.add.v4.f32 [%0], {%1, %2, %3, %4};"
                                 :: "l"(hp1 + q * 4), "f"(f0), "f"(f1), "f"(f2), "f"(f3)
                                 : "memory");
                }
            }
        }
        __syncthreads();
        pos = segEnd;
    }
}

// ---------------- edge kernel, H->OUT: thread-per-edge, f32x2 ----------------
__global__ void __launch_bounds__(256, 4) k_edge16(const float* __restrict__ x,
                                                   const float* __restrict__ W,
                                                   float* __restrict__ h) {
    __shared__ float Ws[H_DIM * OUT_DIM];
    int base = blockIdx.x * 256;
    int lim  = min(base + 256, E_EDGES);
    int pos  = base;
    while (pos < lim) {
        int r      = g_edges[pos].z;
        int segEnd = min(lim, g_off[r + 1]);
        ((float4*)Ws)[threadIdx.x] =
            ((const float4*)(W + r * (H_DIM * OUT_DIM)))[threadIdx.x];
        __syncthreads();

        int e = pos + threadIdx.x;
        if (e < segEnd) {
            int4  ed  = g_edges[e];
            const float* xv = x + ed.x * H_DIM;
            unsigned long long acc[8];
#pragma unroll
            for (int j = 0; j < 8; j++) acc[j] = 0ull;

#pragma unroll
            for (int ic = 0; ic < 8; ic++) {
                float4 a0 = *(const float4*)(xv + ic * 8);
                float4 a1 = *(const float4*)(xv + ic * 8 + 4);
                float xs[8] = {a0.x, a0.y, a0.z, a0.w, a1.x, a1.y, a1.z, a1.w};
#pragma unroll
                for (int i = 0; i < 8; i++) {
                    unsigned long long A;
                    DUP2(A, xs[i]);
                    const float* Wrow = Ws + (ic * 8 + i) * OUT_DIM;
#pragma unroll
                    for (int j = 0; j < 4; j++) {
                        ulonglong2 w = *(const ulonglong2*)(Wrow + j * 4);
                        FMA2(acc[2 * j],     A, w.x);
                        FMA2(acc[2 * j + 1], A, w.y);
                    }
                }
            }
            unsigned long long NN;
            DUP2(NN, __int_as_float(ed.w));
#pragma unroll
            for (int j = 0; j < 8; j++) MUL2(acc[j], NN);

            float* hp = h + ed.y * OUT_DIM;
#pragma unroll
            for (int q = 0; q < 4; q++) {
                float f0, f1, f2, f3;
                UNPK2(f0, f1, acc[2 * q]);
                UNPK2(f2, f3, acc[2 * q + 1]);
                asm volatile("red.global.add.v4.f32 [%0], {%1, %2, %3, %4};"
                             :: "l"(hp + q * 4), "f"(f0), "f"(f1), "f"(f2), "f"(f3)
                             : "memory");
            }
        }
        __syncthreads();
        pos = segEnd;
    }
}

// ---------------- launch ----------------
extern "C" void kernel_launch(void* const* d_in, const int* in_sizes, int n_in,
                              void* d_out, int out_size) {
    const float* feats  = (const float*)d_in[0];
    const float* coeff0 = (const float*)d_in[1];
    const float* bases0 = (const float*)d_in[2];
    const float* bias0  = (const float*)d_in[3];
    const float* coeff1 = (const float*)d_in[4];
    const float* bases1 = (const float*)d_in[5];
    const float* bias1  = (const float*)d_in[6];
    const float* coeff2 = (const float*)d_in[7];
    const float* bases2 = (const float*)d_in[8];
    const float* bias2  = (const float*)d_in[9];
    const int*   src    = (const int*)d_in[10];
    const int*   dst    = (const int*)d_in[11];
    const int*   etype  = (const int*)d_in[12];
    const float* norm   = (const float*)d_in[13];
    float*       out    = (float*)d_out;

    const int SB = (E_EDGES + SC_EPB - 1) / SC_EPB;
    const int EB = (E_EDGES + 255) / 256;

    k_zero_cnt<<<1, 128>>>();
    k_hist<<<SB, 256>>>(etype);
    k_scan<<<1, 32>>>();
    k_scatter<<<SB, 256>>>(src, dst, etype, norm);

    k_W<H_DIM><<<(R_REL * H_DIM * H_DIM + 255) / 256, 256>>>(coeff0, bases0, 0);
    k_W<H_DIM><<<(R_REL * H_DIM * H_DIM + 255) / 256, 256>>>(coeff1, bases1, 1);
    k_W<OUT_DIM><<<(R_REL * H_DIM * OUT_DIM + 255) / 256, 256>>>(coeff2, bases2, 2);

    const int NB64 = (N_NODES * H_DIM / 4 + 255) / 256;
    const int NB16 = (N_NODES * OUT_DIM / 4 + 255) / 256;

    float *h1, *h2, *W0, *W1, *W2;
    cudaGetSymbolAddress((void**)&h1, g_h1);
    cudaGetSymbolAddress((void**)&h2, g_h2);
    cudaGetSymbolAddress((void**)&W0, g_W0);
    cudaGetSymbolAddress((void**)&W1, g_W1);
    cudaGetSymbolAddress((void**)&W2, g_W2);

    // layer 0: feats -> h1
    k_init64<<<NB64, 256>>>(bias0, h1);
    k_edge64<<<EB, 256>>>(feats, W0, h1);
    k_relu<<<NB64, 256>>>(h1);

    // layer 1: relu(h1) -> h2
    k_init64<<<NB64, 256>>>(bias1, h2);
    k_edge64<<<EB, 256>>>(h1, W1, h2);
    k_relu<<<NB64, 256>>>(h2);

    // layer 2: relu(h2) -> out
    k_init16<<<NB16, 256>>>(bias2, out);
    k_edge16<<<EB, 256>>>(h2, W2, out);
}